// round 2
// baseline (speedup 1.0000x reference)
#include <cuda_runtime.h>
#include <string.h>

#define N_IN   200000
#define N_OUT  400000
#define K3     27
#define MP     100000
#define C      128
#define EPS    1e-5f

#define TILE_M 64
#define NTHR   256

// persistent device scratch for BN statistics (no allocations allowed)
__device__ float g_sum[C];
__device__ float g_sumsq[C];
__device__ float g_scale[C];
__device__ float g_shift[C];

// ---------------------------------------------------------------------------
// helpers
// ---------------------------------------------------------------------------

// packed dual-FMA: d.{lo,hi} += a.{lo,hi} * b.{lo,hi}   (2x FFMA throughput)
__device__ __forceinline__ void fma2(unsigned long long& d,
                                     unsigned long long a,
                                     unsigned long long b) {
    asm("fma.rn.f32x2 %0, %1, %2, %0;" : "+l"(d) : "l"(a), "l"(b));
}

// duplicate a scalar float into both halves of an f32x2 register
__device__ __forceinline__ unsigned long long pack2(float x) {
    unsigned long long r;
    unsigned int xi = __float_as_uint(x);
    asm("mov.b64 %0, {%1, %1};" : "=l"(r) : "r"(xi));
    return r;
}

// vectorized global reduction-add (one L2 atomic op for 16 bytes)
__device__ __forceinline__ void red_v4(float* p, float a, float b, float c, float d) {
    asm volatile("red.global.add.v4.f32 [%0], {%1, %2, %3, %4};"
                 :: "l"(p), "f"(a), "f"(b), "f"(c), "f"(d) : "memory");
}

// ---------------------------------------------------------------------------
// kernel 1: zero output buffer + stats accumulators
// ---------------------------------------------------------------------------
__global__ void zero_kernel(float* __restrict__ out) {
    const size_t n4 = (size_t)N_OUT * (C / 4);
    const size_t stride = (size_t)gridDim.x * blockDim.x;
    float4 z = make_float4(0.f, 0.f, 0.f, 0.f);
    for (size_t i = (size_t)blockIdx.x * blockDim.x + threadIdx.x; i < n4; i += stride)
        ((float4*)out)[i] = z;
    if (blockIdx.x == 0 && threadIdx.x < C) {
        g_sum[threadIdx.x]   = 0.f;
        g_sumsq[threadIdx.x] = 0.f;
    }
}

// ---------------------------------------------------------------------------
// kernel 2: gather -> [64,128]x[128,128] GEMM (f32x2 packed FMA) -> scatter-add
// grid: (ceil(MP/64), 27), block: 256 threads
// dyn smem: W[k] 64KB + A tile 32KB + maps
// ---------------------------------------------------------------------------
__global__ void __launch_bounds__(NTHR, 2)
scatter_gemm(const float* __restrict__ feats,
             const float* __restrict__ W,
             const int*   __restrict__ in_maps,
             const int*   __restrict__ out_maps,
             float*       __restrict__ out) {
    extern __shared__ float smem[];
    float* Ws = smem;                       // [128][128] W[k], row = c_in
    float* As = smem + C * C;               // [64][128] gathered feats
    int*   im_s = (int*)(As + TILE_M * C);  // [64]
    int*   om_s = im_s + TILE_M;            // [64]

    const int k   = blockIdx.y;
    const int m0  = blockIdx.x * TILE_M;
    const int tid = threadIdx.x;

    // stage maps
    if (tid < TILE_M) {
        int m = m0 + tid;
        int vi = 0, vo = -1;
        if (m < MP) {
            vi = in_maps[k * MP + m];
            vo = out_maps[k * MP + m];
        }
        im_s[tid] = vi;
        om_s[tid] = vo;
    }

    // stage W[k] (coalesced float4)
    {
        const float4* Wg  = (const float4*)(W + (size_t)k * C * C);
        float4*       Ws4 = (float4*)Ws;
#pragma unroll
        for (int i = 0; i < (C * C / 4) / NTHR; ++i)   // 16 iters
            Ws4[i * NTHR + tid] = Wg[i * NTHR + tid];
    }
    __syncthreads();

    // gather A tile: warp handles one row's 512B contiguously (coalesced LDG)
    {
        float4* As4 = (float4*)As;
#pragma unroll
        for (int it = 0; it < (TILE_M * (C / 4)) / NTHR; ++it) {  // 8 iters
            int idx = it * NTHR + tid;
            int r   = idx >> 5;     // row within tile
            int c4  = idx & 31;     // float4 column
            int row = im_s[r];
            As4[idx] = ((const float4*)(feats + (size_t)row * C))[c4];
        }
    }
    __syncthreads();

    // register-blocked GEMM: thread computes 4 rows x 8 cols (4 f32x2 pairs)
    const int tx = tid & 15;   // col group: cols [tx*8, tx*8+8)
    const int ty = tid >> 4;   // row group: rows [ty*4, ty*4+4)

    unsigned long long acc[4][4];
#pragma unroll
    for (int r = 0; r < 4; ++r)
#pragma unroll
        for (int p = 0; p < 4; ++p) acc[r][p] = 0ULL;

    const float4*     As4 = (const float4*)As;
    const ulonglong2* Ws2 = (const ulonglong2*)Ws;

#pragma unroll 2
    for (int kk4 = 0; kk4 < 32; ++kk4) {
        float4 a4[4];
#pragma unroll
        for (int r = 0; r < 4; ++r)
            a4[r] = As4[(ty * 4 + r) * 32 + kk4];   // 4 k-values per row

#pragma unroll
        for (int j = 0; j < 4; ++j) {
            const int kk = kk4 * 4 + j;
            // W row stride: 128 floats = 32 ulonglong2 (BUG FIX: was 16)
            ulonglong2 b0 = Ws2[kk * 32 + tx * 2];      // cols tx*8 .. +3
            ulonglong2 b1 = Ws2[kk * 32 + tx * 2 + 1];  // cols tx*8+4 .. +7
#pragma unroll
            for (int r = 0; r < 4; ++r) {
                float av = (j == 0) ? a4[r].x : (j == 1) ? a4[r].y
                         : (j == 2) ? a4[r].z : a4[r].w;
                unsigned long long ad = pack2(av);
                fma2(acc[r][0], ad, b0.x);
                fma2(acc[r][1], ad, b0.y);
                fma2(acc[r][2], ad, b1.x);
                fma2(acc[r][3], ad, b1.y);
            }
        }
    }

    // scatter-add: vectorized global reductions (2 x red.v4 per row)
#pragma unroll
    for (int r = 0; r < 4; ++r) {
        int orow = om_s[ty * 4 + r];
        if (orow >= 0) {
            float* dst = out + (size_t)orow * C + tx * 8;
            float2 f0, f1, f2, f3;
            memcpy(&f0, &acc[r][0], 8);
            memcpy(&f1, &acc[r][1], 8);
            memcpy(&f2, &acc[r][2], 8);
            memcpy(&f3, &acc[r][3], 8);
            red_v4(dst,     f0.x, f0.y, f1.x, f1.y);
            red_v4(dst + 4, f2.x, f2.y, f3.x, f3.y);
        }
    }
}

// ---------------------------------------------------------------------------
// kernel 3: per-channel sum / sumsq
// ---------------------------------------------------------------------------
__global__ void stats_kernel(const float* __restrict__ out) {
    __shared__ float4 ssum[256];
    __shared__ float4 ssq[256];
    const int tid = threadIdx.x;
    const int c4  = tid & 31;                       // float4 column within row
    const int g   = (blockIdx.x * 256 + tid) >> 5;  // row-group id
    const int ng  = (gridDim.x * 256) >> 5;

    float4 s = make_float4(0.f, 0.f, 0.f, 0.f);
    float4 q = make_float4(0.f, 0.f, 0.f, 0.f);
    const float4* o4 = (const float4*)out;
    for (int r = g; r < N_OUT; r += ng) {
        float4 v = o4[(size_t)r * 32 + c4];
        s.x += v.x; s.y += v.y; s.z += v.z; s.w += v.w;
        q.x += v.x * v.x; q.y += v.y * v.y; q.z += v.z * v.z; q.w += v.w * v.w;
    }
    ssum[tid] = s;
    ssq[tid]  = q;
    __syncthreads();
#pragma unroll
    for (int st = 128; st >= 32; st >>= 1) {
        if (tid < st) {
            ssum[tid].x += ssum[tid + st].x; ssum[tid].y += ssum[tid + st].y;
            ssum[tid].z += ssum[tid + st].z; ssum[tid].w += ssum[tid + st].w;
            ssq[tid].x  += ssq[tid + st].x;  ssq[tid].y  += ssq[tid + st].y;
            ssq[tid].z  += ssq[tid + st].z;  ssq[tid].w  += ssq[tid + st].w;
        }
        __syncthreads();
    }
    if (tid < 32) {
        atomicAdd(&g_sum[c4 * 4 + 0], ssum[tid].x);
        atomicAdd(&g_sum[c4 * 4 + 1], ssum[tid].y);
        atomicAdd(&g_sum[c4 * 4 + 2], ssum[tid].z);
        atomicAdd(&g_sum[c4 * 4 + 3], ssum[tid].w);
        atomicAdd(&g_sumsq[c4 * 4 + 0], ssq[tid].x);
        atomicAdd(&g_sumsq[c4 * 4 + 1], ssq[tid].y);
        atomicAdd(&g_sumsq[c4 * 4 + 2], ssq[tid].z);
        atomicAdd(&g_sumsq[c4 * 4 + 3], ssq[tid].w);
    }
}

// ---------------------------------------------------------------------------
// kernel 4: fold stats into per-channel scale/shift
// ---------------------------------------------------------------------------
__global__ void finalize_kernel(const float* __restrict__ gamma,
                                const float* __restrict__ beta) {
    const int c = threadIdx.x;
    const float inv_n = 1.0f / (float)N_OUT;
    float mean = g_sum[c] * inv_n;
    float var  = g_sumsq[c] * inv_n - mean * mean;
    float sc   = rsqrtf(var + EPS) * gamma[c];
    g_scale[c] = sc;
    g_shift[c] = beta[c] - mean * sc;
}

// ---------------------------------------------------------------------------
// kernel 5: in-place normalize
// ---------------------------------------------------------------------------
__global__ void norm_kernel(float* __restrict__ out) {
    const float4* sc4 = (const float4*)g_scale;
    const float4* sh4 = (const float4*)g_shift;
    const size_t n4 = (size_t)N_OUT * (C / 4);
    const size_t stride = (size_t)gridDim.x * blockDim.x;
    for (size_t i = (size_t)blockIdx.x * blockDim.x + threadIdx.x; i < n4; i += stride) {
        int c4 = (int)(i & 31);
        float4 v = ((float4*)out)[i];
        float4 s = sc4[c4];
        float4 h = sh4[c4];
        v.x = v.x * s.x + h.x;
        v.y = v.y * s.y + h.y;
        v.z = v.z * s.z + h.z;
        v.w = v.w * s.w + h.w;
        ((float4*)out)[i] = v;
    }
}

// ---------------------------------------------------------------------------
// launch
// ---------------------------------------------------------------------------
extern "C" void kernel_launch(void* const* d_in, const int* in_sizes, int n_in,
                              void* d_out, int out_size) {
    const float* feats    = (const float*)d_in[0];
    const float* W        = (const float*)d_in[1];
    const float* gamma    = (const float*)d_in[2];
    const float* beta     = (const float*)d_in[3];
    const int*   in_maps  = (const int*)d_in[4];
    const int*   out_maps = (const int*)d_in[5];
    float* out = (float*)d_out;

    const size_t SMEM = (size_t)(C * C + TILE_M * C) * sizeof(float)
                      + 2 * TILE_M * sizeof(int);   // 98816 B
    cudaFuncSetAttribute(scatter_gemm,
                         cudaFuncAttributeMaxDynamicSharedMemorySize, (int)SMEM);

    zero_kernel<<<1184, 256>>>(out);

    dim3 grid((MP + TILE_M - 1) / TILE_M, K3);
    scatter_gemm<<<grid, NTHR, SMEM>>>(feats, W, in_maps, out_maps, out);

    stats_kernel<<<1184, 256>>>(out);
    finalize_kernel<<<1, C>>>(gamma, beta);
    norm_kernel<<<1184, 256>>>(out);
}

// round 4
// speedup vs baseline: 2.7319x; 2.7319x over previous
#include <cuda_runtime.h>
#include <cuda_fp16.h>
#include <cstdint>

#define N_IN   200000
#define N_OUT  400000
#define K3     27
#define MP     100000
#define C      128
#define EPS    1e-5f

#define TILE_M 128
#define NTHR   256

// ---------------------------------------------------------------------------
// persistent device scratch (allocations are forbidden)
// ---------------------------------------------------------------------------
__device__ float g_sum[C];
__device__ float g_sumsq[C];
__device__ float g_scale[C];
__device__ float g_shift[C];

__device__ __half g_fh[(size_t)N_IN * C];          // feats, fp16
__device__ __half g_wt[(size_t)K3 * C * C];        // W^T: [k][n(c_out)][c_in], fp16

// ---------------------------------------------------------------------------
// helpers
// ---------------------------------------------------------------------------
__device__ __forceinline__ uint32_t smem_u32(const void* p) {
    uint32_t a;
    asm("{ .reg .u64 t; cvta.to.shared.u64 t, %1; cvt.u32.u64 %0, t; }"
        : "=r"(a) : "l"(p));
    return a;
}
__device__ __forceinline__ void red_v4(float* p, float a, float b, float c, float d) {
    asm volatile("red.global.add.v4.f32 [%0], {%1, %2, %3, %4};"
                 :: "l"(p), "f"(a), "f"(b), "f"(c), "f"(d) : "memory");
}
__device__ __forceinline__ void ldsm_x4(uint32_t& r0, uint32_t& r1,
                                        uint32_t& r2, uint32_t& r3, uint32_t addr) {
    asm volatile("ldmatrix.sync.aligned.m8n8.x4.shared.b16 {%0,%1,%2,%3}, [%4];"
                 : "=r"(r0), "=r"(r1), "=r"(r2), "=r"(r3) : "r"(addr));
}
__device__ __forceinline__ void mma16816(float* c, uint32_t a0, uint32_t a1,
                                         uint32_t a2, uint32_t a3,
                                         uint32_t b0, uint32_t b1) {
    asm volatile(
        "mma.sync.aligned.m16n8k16.row.col.f32.f16.f16.f32 "
        "{%0,%1,%2,%3}, {%4,%5,%6,%7}, {%8,%9}, {%0,%1,%2,%3};"
        : "+f"(c[0]), "+f"(c[1]), "+f"(c[2]), "+f"(c[3])
        : "r"(a0), "r"(a1), "r"(a2), "r"(a3), "r"(b0), "r"(b1));
}

// ---------------------------------------------------------------------------
// kernel 1: zero output + stats
// ---------------------------------------------------------------------------
__global__ void zero_kernel(float* __restrict__ out) {
    const size_t n4 = (size_t)N_OUT * (C / 4);
    const size_t stride = (size_t)gridDim.x * blockDim.x;
    float4 z = make_float4(0.f, 0.f, 0.f, 0.f);
    for (size_t i = (size_t)blockIdx.x * blockDim.x + threadIdx.x; i < n4; i += stride)
        ((float4*)out)[i] = z;
    if (blockIdx.x == 0 && threadIdx.x < C) {
        g_sum[threadIdx.x]   = 0.f;
        g_sumsq[threadIdx.x] = 0.f;
    }
}

// ---------------------------------------------------------------------------
// kernel 2: feats fp32 -> fp16
// ---------------------------------------------------------------------------
__global__ void conv_feats(const float* __restrict__ feats) {
    const size_t n4 = (size_t)N_IN * (C / 4);
    const size_t stride = (size_t)gridDim.x * blockDim.x;
    for (size_t i = (size_t)blockIdx.x * blockDim.x + threadIdx.x; i < n4; i += stride) {
        float4 v = ((const float4*)feats)[i];
        __half h[4];
        h[0] = __float2half_rn(v.x);
        h[1] = __float2half_rn(v.y);
        h[2] = __float2half_rn(v.z);
        h[3] = __float2half_rn(v.w);
        ((uint2*)g_fh)[i] = *(uint2*)h;
    }
}

// ---------------------------------------------------------------------------
// kernel 3: W transpose -> fp16:  g_wt[k][n][c] = W[k][c][n]
// ---------------------------------------------------------------------------
__global__ void conv_W(const float* __restrict__ W) {
    const size_t n = (size_t)K3 * C * C;
    const size_t stride = (size_t)gridDim.x * blockDim.x;
    for (size_t i = (size_t)blockIdx.x * blockDim.x + threadIdx.x; i < n; i += stride) {
        int c  = (int)(i & (C - 1));
        int nn = (int)((i >> 7) & (C - 1));
        int k  = (int)(i >> 14);
        g_wt[i] = __float2half_rn(W[(size_t)k * C * C + (size_t)c * C + nn]);
    }
}

// ---------------------------------------------------------------------------
// kernel 4: gather -> HMMA GEMM -> scatter-add
// grid: (ceil(MP/128), 27), block 256 (8 warps, 4x2 warp grid of 32x64 tiles)
// ---------------------------------------------------------------------------
#define PAD_C  136                       // 128 + 8 fp16 padding
#define SM_IM  0
#define SM_OM  512
#define SM_A   1024
#define SM_B   (SM_A + TILE_M * PAD_C * 2)      // 1024 + 34816
#define SM_TOT (SM_B + C * PAD_C * 2)           // + 34816 = 70656

__global__ void __launch_bounds__(NTHR, 2)
scatter_gemm(const int* __restrict__ in_maps,
             const int* __restrict__ out_maps,
             float*     __restrict__ out) {
    extern __shared__ char smem[];
    const uint32_t smb = smem_u32(smem);
    const int tid  = threadIdx.x;
    const int wid  = tid >> 5;
    const int lane = tid & 31;
    const int k    = blockIdx.y;
    const int m0   = blockIdx.x * TILE_M;

    int* im_s = (int*)(smem + SM_IM);
    int* om_s = (int*)(smem + SM_OM);

    // stage maps
    if (tid < TILE_M) {
        int m = m0 + tid;
        int vi = 0, vo = -1;
        if (m < MP) {
            vi = in_maps[(size_t)k * MP + m];
            vo = out_maps[(size_t)k * MP + m];
        }
        im_s[tid] = vi;
        om_s[tid] = vo;
    }
    __syncthreads();

    // B tile: W^T[k] (dense) into padded smem
    {
        const uint4* bg = (const uint4*)(g_wt + (size_t)k * C * C);
#pragma unroll
        for (int it = 0; it < 2048 / NTHR; ++it) {     // 8 iters
            int idx = it * NTHR + tid;
            int row = idx >> 4;
            int c8  = idx & 15;
            *(uint4*)(smem + SM_B + (row * PAD_C + c8 * 8) * 2) = bg[idx];
        }
    }
    // A tile: gathered feats rows
    {
#pragma unroll
        for (int it = 0; it < 2048 / NTHR; ++it) {     // 8 iters
            int idx = it * NTHR + tid;
            int row = idx >> 4;
            int c8  = idx & 15;
            const uint4 v = *(const uint4*)(g_fh + (size_t)im_s[row] * C + c8 * 8);
            *(uint4*)(smem + SM_A + (row * PAD_C + c8 * 8) * 2) = v;
        }
    }
    __syncthreads();

    // warp tile: 32 rows x 64 cols
    const int wm = (wid & 3) * 32;     // row base
    const int wn = (wid >> 2) * 64;    // col base

    float acc[2][8][4];
#pragma unroll
    for (int mb = 0; mb < 2; ++mb)
#pragma unroll
        for (int nb = 0; nb < 8; ++nb)
#pragma unroll
            for (int j = 0; j < 4; ++j) acc[mb][nb][j] = 0.f;

    // per-lane ldmatrix base addresses
    // A: rows m + (lane&15), col (lane>>4)*8
    const uint32_t aAddr = smb + SM_A
        + ((uint32_t)(wm + (lane & 15)) * PAD_C + ((lane >> 4) << 3)) * 2;
    // B: rows n + ((lane>>4)<<3) + (lane&7), col ((lane>>3)&1)*8
    const uint32_t bAddr = smb + SM_B
        + ((uint32_t)(wn + ((lane >> 4) << 3) + (lane & 7)) * PAD_C
           + (((lane >> 3) & 1) << 3)) * 2;

#pragma unroll
    for (int ks = 0; ks < 8; ++ks) {
        const uint32_t kb = ks * 32;       // 16 halves = 32 bytes
        uint32_t a[2][4];
#pragma unroll
        for (int mb = 0; mb < 2; ++mb)
            ldsm_x4(a[mb][0], a[mb][1], a[mb][2], a[mb][3],
                    aAddr + mb * (16 * PAD_C * 2) + kb);
        uint32_t b[4][4];
#pragma unroll
        for (int g = 0; g < 4; ++g)
            ldsm_x4(b[g][0], b[g][1], b[g][2], b[g][3],
                    bAddr + g * (16 * PAD_C * 2) + kb);
#pragma unroll
        for (int mb = 0; mb < 2; ++mb)
#pragma unroll
            for (int g = 0; g < 4; ++g) {
                mma16816(acc[mb][2 * g],     a[mb][0], a[mb][1], a[mb][2], a[mb][3],
                         b[g][0], b[g][1]);
                mma16816(acc[mb][2 * g + 1], a[mb][0], a[mb][1], a[mb][2], a[mb][3],
                         b[g][2], b[g][3]);
            }
    }

    // epilogue: pair lanes via shfl to form 16B quads, one red.v4 each
    const bool hi  = (lane & 1);
    const int  cb4 = (lane & 2) << 1;             // 0 or 4 within n8 block
    const int  rloc = wm + (lane >> 2) + (hi ? 8 : 0);

#pragma unroll
    for (int mb = 0; mb < 2; ++mb) {
        const int orow = om_s[rloc + mb * 16];
#pragma unroll
        for (int nb = 0; nb < 8; ++nb) {
            float f0 = acc[mb][nb][0], f1 = acc[mb][nb][1];
            float f2 = acc[mb][nb][2], f3 = acc[mb][nb][3];
            float o0 = __shfl_xor_sync(0xFFFFFFFF, f0, 1);
            float o1 = __shfl_xor_sync(0xFFFFFFFF, f1, 1);
            float o2 = __shfl_xor_sync(0xFFFFFFFF, f2, 1);
            float o3 = __shfl_xor_sync(0xFFFFFFFF, f3, 1);
            if (orow >= 0) {
                float* dst = out + (size_t)orow * C + wn + nb * 8 + cb4;
                if (!hi) red_v4(dst, f0, f1, o0, o1);   // row r,   cols cb4..cb4+3
                else     red_v4(dst, o2, o3, f2, f3);   // row r+8, cols cb4..cb4+3
            }
        }
    }
}

// ---------------------------------------------------------------------------
// kernel 5: per-channel sum / sumsq
// ---------------------------------------------------------------------------
__global__ void stats_kernel(const float* __restrict__ out) {
    __shared__ float4 ssum[256];
    __shared__ float4 ssq[256];
    const int tid = threadIdx.x;
    const int c4  = tid & 31;
    const int g   = (blockIdx.x * 256 + tid) >> 5;
    const int ng  = (gridDim.x * 256) >> 5;

    float4 s = make_float4(0.f, 0.f, 0.f, 0.f);
    float4 q = make_float4(0.f, 0.f, 0.f, 0.f);
    const float4* o4 = (const float4*)out;
    for (int r = g; r < N_OUT; r += ng) {
        float4 v = o4[(size_t)r * 32 + c4];
        s.x += v.x; s.y += v.y; s.z += v.z; s.w += v.w;
        q.x += v.x * v.x; q.y += v.y * v.y; q.z += v.z * v.z; q.w += v.w * v.w;
    }
    ssum[tid] = s;
    ssq[tid]  = q;
    __syncthreads();
#pragma unroll
    for (int st = 128; st >= 32; st >>= 1) {
        if (tid < st) {
            ssum[tid].x += ssum[tid + st].x; ssum[tid].y += ssum[tid + st].y;
            ssum[tid].z += ssum[tid + st].z; ssum[tid].w += ssum[tid + st].w;
            ssq[tid].x  += ssq[tid + st].x;  ssq[tid].y  += ssq[tid + st].y;
            ssq[tid].z  += ssq[tid + st].z;  ssq[tid].w  += ssq[tid + st].w;
        }
        __syncthreads();
    }
    if (tid < 32) {
        atomicAdd(&g_sum[c4 * 4 + 0], ssum[tid].x);
        atomicAdd(&g_sum[c4 * 4 + 1], ssum[tid].y);
        atomicAdd(&g_sum[c4 * 4 + 2], ssum[tid].z);
        atomicAdd(&g_sum[c4 * 4 + 3], ssum[tid].w);
        atomicAdd(&g_sumsq[c4 * 4 + 0], ssq[tid].x);
        atomicAdd(&g_sumsq[c4 * 4 + 1], ssq[tid].y);
        atomicAdd(&g_sumsq[c4 * 4 + 2], ssq[tid].z);
        atomicAdd(&g_sumsq[c4 * 4 + 3], ssq[tid].w);
    }
}

// ---------------------------------------------------------------------------
// kernel 6: fold stats
// ---------------------------------------------------------------------------
__global__ void finalize_kernel(const float* __restrict__ gamma,
                                const float* __restrict__ beta) {
    const int c = threadIdx.x;
    const float inv_n = 1.0f / (float)N_OUT;
    float mean = g_sum[c] * inv_n;
    float var  = g_sumsq[c] * inv_n - mean * mean;
    float sc   = rsqrtf(var + EPS) * gamma[c];
    g_scale[c] = sc;
    g_shift[c] = beta[c] - mean * sc;
}

// ---------------------------------------------------------------------------
// kernel 7: in-place normalize
// ---------------------------------------------------------------------------
__global__ void norm_kernel(float* __restrict__ out) {
    const float4* sc4 = (const float4*)g_scale;
    const float4* sh4 = (const float4*)g_shift;
    const size_t n4 = (size_t)N_OUT * (C / 4);
    const size_t stride = (size_t)gridDim.x * blockDim.x;
    for (size_t i = (size_t)blockIdx.x * blockDim.x + threadIdx.x; i < n4; i += stride) {
        int c4 = (int)(i & 31);
        float4 v = ((float4*)out)[i];
        float4 s = sc4[c4];
        float4 h = sh4[c4];
        v.x = v.x * s.x + h.x;
        v.y = v.y * s.y + h.y;
        v.z = v.z * s.z + h.z;
        v.w = v.w * s.w + h.w;
        ((float4*)out)[i] = v;
    }
}

// ---------------------------------------------------------------------------
// launch
// ---------------------------------------------------------------------------
extern "C" void kernel_launch(void* const* d_in, const int* in_sizes, int n_in,
                              void* d_out, int out_size) {
    const float* feats    = (const float*)d_in[0];
    const float* W        = (const float*)d_in[1];
    const float* gamma    = (const float*)d_in[2];
    const float* beta     = (const float*)d_in[3];
    const int*   in_maps  = (const int*)d_in[4];
    const int*   out_maps = (const int*)d_in[5];
    float* out = (float*)d_out;

    cudaFuncSetAttribute(scatter_gemm,
                         cudaFuncAttributeMaxDynamicSharedMemorySize, SM_TOT);

    zero_kernel<<<1184, 256>>>(out);
    conv_feats<<<1184, 256>>>(feats);
    conv_W<<<432, 256>>>(W);

    dim3 grid((MP + TILE_M - 1) / TILE_M, K3);
    scatter_gemm<<<grid, NTHR, SM_TOT>>>(in_maps, out_maps, out);

    stats_kernel<<<1184, 256>>>(out);
    finalize_kernel<<<1, C>>>(gamma, beta);
    norm_kernel<<<1184, 256>>>(out);
}

// round 5
// speedup vs baseline: 3.7095x; 1.3578x over previous
#include <cuda_runtime.h>
#include <cuda_fp16.h>
#include <cstdint>

#define N_IN   200000
#define N_OUT  400000
#define K3     27
#define MP     100000
#define C      128
#define EPS    1e-5f

#define TILE_M 128
#define NTHR   256
#define NTILES 782                         // ceil(MP/128)
#define TASKS  (K3 * NTILES)               // 21114
#define TPB    72
#define GRID_MAIN ((TASKS + TPB - 1) / TPB)  // 294

// ---------------------------------------------------------------------------
// persistent device scratch (allocations are forbidden)
// ---------------------------------------------------------------------------
__device__ float g_sum[C];
__device__ float g_sumsq[C];
__device__ float g_scale[C];
__device__ float g_shift[C];

__device__ __half g_fh[(size_t)N_IN * C];      // feats, fp16
__device__ __half g_wt[(size_t)K3 * C * C];    // W^T: [k][n(c_out)][c_in], fp16

// ---------------------------------------------------------------------------
// helpers
// ---------------------------------------------------------------------------
__device__ __forceinline__ uint32_t smem_u32(const void* p) {
    uint32_t a;
    asm("{ .reg .u64 t; cvta.to.shared.u64 t, %1; cvt.u32.u64 %0, t; }"
        : "=r"(a) : "l"(p));
    return a;
}
__device__ __forceinline__ void red_v4(float* p, float a, float b, float c, float d) {
    asm volatile("red.global.add.v4.f32 [%0], {%1, %2, %3, %4};"
                 :: "l"(p), "f"(a), "f"(b), "f"(c), "f"(d) : "memory");
}
__device__ __forceinline__ void ldsm_x4(uint32_t& r0, uint32_t& r1,
                                        uint32_t& r2, uint32_t& r3, uint32_t addr) {
    asm volatile("ldmatrix.sync.aligned.m8n8.x4.shared.b16 {%0,%1,%2,%3}, [%4];"
                 : "=r"(r0), "=r"(r1), "=r"(r2), "=r"(r3) : "r"(addr));
}
__device__ __forceinline__ void mma16816(float* c, uint32_t a0, uint32_t a1,
                                         uint32_t a2, uint32_t a3,
                                         uint32_t b0, uint32_t b1) {
    asm volatile(
        "mma.sync.aligned.m16n8k16.row.col.f32.f16.f16.f32 "
        "{%0,%1,%2,%3}, {%4,%5,%6,%7}, {%8,%9}, {%0,%1,%2,%3};"
        : "+f"(c[0]), "+f"(c[1]), "+f"(c[2]), "+f"(c[3])
        : "r"(a0), "r"(a1), "r"(a2), "r"(a3), "r"(b0), "r"(b1));
}
__device__ __forceinline__ void cp16(uint32_t dst, const void* src) {
    asm volatile("cp.async.cg.shared.global [%0], [%1], 16;"
                 :: "r"(dst), "l"(src) : "memory");
}
#define CP_COMMIT()  asm volatile("cp.async.commit_group;" ::: "memory")
#define CP_WAIT(N)   asm volatile("cp.async.wait_group %0;" :: "n"(N) : "memory")

// ---------------------------------------------------------------------------
// kernel 1: zero output + stats
// ---------------------------------------------------------------------------
__global__ void zero_kernel(float* __restrict__ out) {
    const size_t n4 = (size_t)N_OUT * (C / 4);
    const size_t stride = (size_t)gridDim.x * blockDim.x;
    float4 z = make_float4(0.f, 0.f, 0.f, 0.f);
    for (size_t i = (size_t)blockIdx.x * blockDim.x + threadIdx.x; i < n4; i += stride)
        ((float4*)out)[i] = z;
    if (blockIdx.x == 0 && threadIdx.x < C) {
        g_sum[threadIdx.x]   = 0.f;
        g_sumsq[threadIdx.x] = 0.f;
    }
}

// ---------------------------------------------------------------------------
// kernel 2: feats fp32 -> fp16
// ---------------------------------------------------------------------------
__global__ void conv_feats(const float* __restrict__ feats) {
    const size_t n4 = (size_t)N_IN * (C / 4);
    const size_t stride = (size_t)gridDim.x * blockDim.x;
    for (size_t i = (size_t)blockIdx.x * blockDim.x + threadIdx.x; i < n4; i += stride) {
        float4 v = ((const float4*)feats)[i];
        __half h[4];
        h[0] = __float2half_rn(v.x);
        h[1] = __float2half_rn(v.y);
        h[2] = __float2half_rn(v.z);
        h[3] = __float2half_rn(v.w);
        ((uint2*)g_fh)[i] = *(uint2*)h;
    }
}

// ---------------------------------------------------------------------------
// kernel 3: W transpose -> fp16:  g_wt[k][n][c] = W[k][c][n]
// ---------------------------------------------------------------------------
__global__ void conv_W(const float* __restrict__ W) {
    const size_t n = (size_t)K3 * C * C;
    const size_t stride = (size_t)gridDim.x * blockDim.x;
    for (size_t i = (size_t)blockIdx.x * blockDim.x + threadIdx.x; i < n; i += stride) {
        int c  = (int)(i & (C - 1));
        int nn = (int)((i >> 7) & (C - 1));
        int k  = (int)(i >> 14);
        g_wt[i] = __float2half_rn(W[(size_t)k * C * C + (size_t)c * C + nn]);
    }
}

// ---------------------------------------------------------------------------
// kernel 4: persistent pipelined gather -> HMMA -> scatter-add
// grid: 294, block 256 (8 warps, 4x2 warp grid of 32x64 output tiles)
// ---------------------------------------------------------------------------
#define PAD_C  136
#define SM_MAPS 0                                 // 2 bufs x 256 ints = 2048 B
#define SM_B    2048                              // 34816 B
#define SM_A0   (SM_B + C * PAD_C * 2)            // 36864
#define SM_A1   (SM_A0 + TILE_M * PAD_C * 2)      // 71680
#define SM_TOT  (SM_A1 + TILE_M * PAD_C * 2)      // 106496

__global__ void __launch_bounds__(NTHR, 2)
scatter_gemm(const int* __restrict__ in_maps,
             const int* __restrict__ out_maps,
             float*     __restrict__ out) {
    extern __shared__ char smem[];
    const uint32_t smb = smem_u32(smem);
    const int tid  = threadIdx.x;
    const int wid  = tid >> 5;
    const int lane = tid & 31;

    int* maps = (int*)(smem + SM_MAPS);        // [2][256]: im[0..127], om[128..255]

    const int start = blockIdx.x * TPB;
    const int end   = min(start + TPB, TASKS);
    if (start >= end) return;

    // ---- lane constants for MMA/epilogue ----
    const int wm = (wid & 3) * 32;
    const int wn = (wid >> 2) * 64;
    const uint32_t aOff = ((uint32_t)(wm + (lane & 15)) * PAD_C + ((lane >> 4) << 3)) * 2;
    const uint32_t bAddr = smb + SM_B
        + ((uint32_t)(wn + ((lane >> 4) << 3) + (lane & 7)) * PAD_C
           + (((lane >> 3) & 1) << 3)) * 2;
    const bool hi  = (lane & 1);
    const int  cb4 = (lane & 2) << 1;
    const int  rloc = wm + (lane >> 2) + (hi ? 8 : 0);

    // ---- prologue: maps(start) -> buf0, then cp.async A(start) -> Abuf0 ----
    {
        const int k0 = start / NTILES, t0 = start % NTILES;
        if (tid < 128) {
            int m = t0 * TILE_M + tid;
            maps[tid] = (m < MP) ? in_maps[(size_t)k0 * MP + m] : 0;
        } else {
            int m = t0 * TILE_M + (tid - 128);
            maps[tid] = (m < MP) ? out_maps[(size_t)k0 * MP + m] : -1;
        }
    }
    __syncthreads();
    {
#pragma unroll
        for (int it = 0; it < 2048 / NTHR; ++it) {
            int idx = it * NTHR + tid;
            int row = idx >> 4, c8 = idx & 15;
            cp16(smb + SM_A0 + (uint32_t)(row * PAD_C + c8 * 8) * 2,
                 g_fh + (size_t)maps[row] * C + c8 * 8);
        }
        CP_COMMIT();
    }

    int cur_k = -1;
    int buf = 0;

    for (int i = start; i < end; ++i) {
        const int k = i / NTILES;
        const bool has_next = (i + 1 < end);
        const int nb = buf ^ 1;

        // prefetch maps(i+1) into other buffer
        if (has_next) {
            const int k2 = (i + 1) / NTILES, t2 = (i + 1) % NTILES;
            if (tid < 128) {
                int m = t2 * TILE_M + tid;
                maps[nb * 256 + tid] = (m < MP) ? in_maps[(size_t)k2 * MP + m] : 0;
            } else {
                int m = t2 * TILE_M + (tid - 128);
                maps[nb * 256 + tid] = (m < MP) ? out_maps[(size_t)k2 * MP + m] : -1;
            }
        }
        __syncthreads();   // publish maps(nb)

        // issue cp.async gather for A(i+1)
        if (has_next) {
            const uint32_t abase = smb + (nb ? SM_A1 : SM_A0);
            const int* imn = maps + nb * 256;
#pragma unroll
            for (int it = 0; it < 2048 / NTHR; ++it) {
                int idx = it * NTHR + tid;
                int row = idx >> 4, c8 = idx & 15;
                cp16(abase + (uint32_t)(row * PAD_C + c8 * 8) * 2,
                     g_fh + (size_t)imn[row] * C + c8 * 8);
            }
            CP_COMMIT();
            CP_WAIT(1);    // A(i) complete
        } else {
            CP_WAIT(0);
        }

        // (re)load B on k change (<= 2x per CTA)
        if (k != cur_k) {
            const uint4* bg = (const uint4*)(g_wt + (size_t)k * C * C);
#pragma unroll
            for (int it = 0; it < 2048 / NTHR; ++it) {
                int idx = it * NTHR + tid;
                int row = idx >> 4, c8 = idx & 15;
                *(uint4*)(smem + SM_B + (row * PAD_C + c8 * 8) * 2) = bg[idx];
            }
            cur_k = k;
        }
        __syncthreads();   // A(i) + B visible

        // ---- MMA mainloop on Abuf[buf] ----
        const uint32_t aAddr = smb + (buf ? SM_A1 : SM_A0) + aOff;

        float acc[2][8][4];
#pragma unroll
        for (int mb = 0; mb < 2; ++mb)
#pragma unroll
            for (int nbt = 0; nbt < 8; ++nbt)
#pragma unroll
                for (int j = 0; j < 4; ++j) acc[mb][nbt][j] = 0.f;

#pragma unroll
        for (int ks = 0; ks < 8; ++ks) {
            const uint32_t kb = ks * 32;
            uint32_t a[2][4];
#pragma unroll
            for (int mb = 0; mb < 2; ++mb)
                ldsm_x4(a[mb][0], a[mb][1], a[mb][2], a[mb][3],
                        aAddr + mb * (16 * PAD_C * 2) + kb);
            uint32_t b[4][4];
#pragma unroll
            for (int g = 0; g < 4; ++g)
                ldsm_x4(b[g][0], b[g][1], b[g][2], b[g][3],
                        bAddr + g * (16 * PAD_C * 2) + kb);
#pragma unroll
            for (int mb = 0; mb < 2; ++mb)
#pragma unroll
                for (int g = 0; g < 4; ++g) {
                    mma16816(acc[mb][2 * g],     a[mb][0], a[mb][1], a[mb][2], a[mb][3],
                             b[g][0], b[g][1]);
                    mma16816(acc[mb][2 * g + 1], a[mb][0], a[mb][1], a[mb][2], a[mb][3],
                             b[g][2], b[g][3]);
                }
        }

        // ---- epilogue: shfl-pair -> red.global.add.v4 ----
        const int* om = maps + buf * 256 + 128;
#pragma unroll
        for (int mb = 0; mb < 2; ++mb) {
            const int orow = om[rloc + mb * 16];
#pragma unroll
            for (int nbt = 0; nbt < 8; ++nbt) {
                float f0 = acc[mb][nbt][0], f1 = acc[mb][nbt][1];
                float f2 = acc[mb][nbt][2], f3 = acc[mb][nbt][3];
                float o0 = __shfl_xor_sync(0xFFFFFFFF, f0, 1);
                float o1 = __shfl_xor_sync(0xFFFFFFFF, f1, 1);
                float o2 = __shfl_xor_sync(0xFFFFFFFF, f2, 1);
                float o3 = __shfl_xor_sync(0xFFFFFFFF, f3, 1);
                if (orow >= 0) {
                    float* dst = out + (size_t)orow * C + wn + nbt * 8 + cb4;
                    if (!hi) red_v4(dst, f0, f1, o0, o1);
                    else     red_v4(dst, o2, o3, f2, f3);
                }
            }
        }

        __syncthreads();   // protect maps[buf]/Abuf[buf] before next iter reuses
        buf ^= 1;
    }
}

// ---------------------------------------------------------------------------
// kernel 5: per-channel sum / sumsq
// ---------------------------------------------------------------------------
__global__ void stats_kernel(const float* __restrict__ out) {
    __shared__ float4 ssum[256];
    __shared__ float4 ssq[256];
    const int tid = threadIdx.x;
    const int c4  = tid & 31;
    const int g   = (blockIdx.x * 256 + tid) >> 5;
    const int ng  = (gridDim.x * 256) >> 5;

    float4 s = make_float4(0.f, 0.f, 0.f, 0.f);
    float4 q = make_float4(0.f, 0.f, 0.f, 0.f);
    const float4* o4 = (const float4*)out;
    for (int r = g; r < N_OUT; r += ng) {
        float4 v = o4[(size_t)r * 32 + c4];
        s.x += v.x; s.y += v.y; s.z += v.z; s.w += v.w;
        q.x += v.x * v.x; q.y += v.y * v.y; q.z += v.z * v.z; q.w += v.w * v.w;
    }
    ssum[tid] = s;
    ssq[tid]  = q;
    __syncthreads();
#pragma unroll
    for (int st = 128; st >= 32; st >>= 1) {
        if (tid < st) {
            ssum[tid].x += ssum[tid + st].x; ssum[tid].y += ssum[tid + st].y;
            ssum[tid].z += ssum[tid + st].z; ssum[tid].w += ssum[tid + st].w;
            ssq[tid].x  += ssq[tid + st].x;  ssq[tid].y  += ssq[tid + st].y;
            ssq[tid].z  += ssq[tid + st].z;  ssq[tid].w  += ssq[tid + st].w;
        }
        __syncthreads();
    }
    if (tid < 32) {
        atomicAdd(&g_sum[c4 * 4 + 0], ssum[tid].x);
        atomicAdd(&g_sum[c4 * 4 + 1], ssum[tid].y);
        atomicAdd(&g_sum[c4 * 4 + 2], ssum[tid].z);
        atomicAdd(&g_sum[c4 * 4 + 3], ssum[tid].w);
        atomicAdd(&g_sumsq[c4 * 4 + 0], ssq[tid].x);
        atomicAdd(&g_sumsq[c4 * 4 + 1], ssq[tid].y);
        atomicAdd(&g_sumsq[c4 * 4 + 2], ssq[tid].z);
        atomicAdd(&g_sumsq[c4 * 4 + 3], ssq[tid].w);
    }
}

// ---------------------------------------------------------------------------
// kernel 6: fold stats
// ---------------------------------------------------------------------------
__global__ void finalize_kernel(const float* __restrict__ gamma,
                                const float* __restrict__ beta) {
    const int c = threadIdx.x;
    const float inv_n = 1.0f / (float)N_OUT;
    float mean = g_sum[c] * inv_n;
    float var  = g_sumsq[c] * inv_n - mean * mean;
    float sc   = rsqrtf(var + EPS) * gamma[c];
    g_scale[c] = sc;
    g_shift[c] = beta[c] - mean * sc;
}

// ---------------------------------------------------------------------------
// kernel 7: in-place normalize
// ---------------------------------------------------------------------------
__global__ void norm_kernel(float* __restrict__ out) {
    const float4* sc4 = (const float4*)g_scale;
    const float4* sh4 = (const float4*)g_shift;
    const size_t n4 = (size_t)N_OUT * (C / 4);
    const size_t stride = (size_t)gridDim.x * blockDim.x;
    for (size_t i = (size_t)blockIdx.x * blockDim.x + threadIdx.x; i < n4; i += stride) {
        int c4 = (int)(i & 31);
        float4 v = ((float4*)out)[i];
        float4 s = sc4[c4];
        float4 h = sh4[c4];
        v.x = v.x * s.x + h.x;
        v.y = v.y * s.y + h.y;
        v.z = v.z * s.z + h.z;
        v.w = v.w * s.w + h.w;
        ((float4*)out)[i] = v;
    }
}

// ---------------------------------------------------------------------------
// launch
// ---------------------------------------------------------------------------
extern "C" void kernel_launch(void* const* d_in, const int* in_sizes, int n_in,
                              void* d_out, int out_size) {
    const float* feats    = (const float*)d_in[0];
    const float* W        = (const float*)d_in[1];
    const float* gamma    = (const float*)d_in[2];
    const float* beta     = (const float*)d_in[3];
    const int*   in_maps  = (const int*)d_in[4];
    const int*   out_maps = (const int*)d_in[5];
    float* out = (float*)d_out;

    cudaFuncSetAttribute(scatter_gemm,
                         cudaFuncAttributeMaxDynamicSharedMemorySize, SM_TOT);

    zero_kernel<<<1184, 256>>>(out);
    conv_feats<<<1184, 256>>>(feats);
    conv_W<<<432, 256>>>(W);

    scatter_gemm<<<GRID_MAIN, NTHR, SM_TOT>>>(in_maps, out_maps, out);

    stats_kernel<<<1184, 256>>>(out);
    finalize_kernel<<<1, C>>>(gamma, beta);
    norm_kernel<<<1184, 256>>>(out);
}

// round 6
// speedup vs baseline: 4.7226x; 1.2731x over previous
#include <cuda_runtime.h>
#include <cuda_fp16.h>
#include <cstdint>

#define N_IN   200000
#define N_OUT  400000
#define K3     27
#define MP     100000
#define C      128
#define EPS    1e-5f

#define TILE_M 128
#define NTHR   256
#define NTILES 782                           // ceil(MP/128)
#define TASKS  (K3 * NTILES)                 // 21114
#define TPB    72
#define GRID_MAIN ((TASKS + TPB - 1) / TPB)  // 294

// ---------------------------------------------------------------------------
// persistent device scratch (allocations are forbidden)
// ---------------------------------------------------------------------------
__device__ float g_sum[C];
__device__ float g_sumsq[C];

__device__ __half g_fh[(size_t)N_IN * C];      // feats, fp16
__device__ __half g_wt[(size_t)K3 * C * C];    // W^T: [k][n(c_out)][c_in], fp16

// ---------------------------------------------------------------------------
// helpers
// ---------------------------------------------------------------------------
__device__ __forceinline__ uint32_t smem_u32(const void* p) {
    uint32_t a;
    asm("{ .reg .u64 t; cvta.to.shared.u64 t, %1; cvt.u32.u64 %0, t; }"
        : "=r"(a) : "l"(p));
    return a;
}
__device__ __forceinline__ void red_v4(float* p, float a, float b, float c, float d) {
    asm volatile("red.global.add.v4.f32 [%0], {%1, %2, %3, %4};"
                 :: "l"(p), "f"(a), "f"(b), "f"(c), "f"(d) : "memory");
}
__device__ __forceinline__ void ldsm_x4(uint32_t& r0, uint32_t& r1,
                                        uint32_t& r2, uint32_t& r3, uint32_t addr) {
    asm volatile("ldmatrix.sync.aligned.m8n8.x4.shared.b16 {%0,%1,%2,%3}, [%4];"
                 : "=r"(r0), "=r"(r1), "=r"(r2), "=r"(r3) : "r"(addr));
}
__device__ __forceinline__ void mma16816(float* c, uint32_t a0, uint32_t a1,
                                         uint32_t a2, uint32_t a3,
                                         uint32_t b0, uint32_t b1) {
    asm volatile(
        "mma.sync.aligned.m16n8k16.row.col.f32.f16.f16.f32 "
        "{%0,%1,%2,%3}, {%4,%5,%6,%7}, {%8,%9}, {%0,%1,%2,%3};"
        : "+f"(c[0]), "+f"(c[1]), "+f"(c[2]), "+f"(c[3])
        : "r"(a0), "r"(a1), "r"(a2), "r"(a3), "r"(b0), "r"(b1));
}
__device__ __forceinline__ void cp16(uint32_t dst, const void* src) {
    asm volatile("cp.async.cg.shared.global [%0], [%1], 16;"
                 :: "r"(dst), "l"(src) : "memory");
}
// zfill variant: copies src_size bytes (0..16), zero-fills the rest
__device__ __forceinline__ void cp16z(uint32_t dst, const void* src, int nbytes) {
    asm volatile("cp.async.ca.shared.global [%0], [%1], 16, %2;"
                 :: "r"(dst), "l"(src), "r"(nbytes) : "memory");
}
#define CP_COMMIT()  asm volatile("cp.async.commit_group;" ::: "memory")
#define CP_WAIT(N)   asm volatile("cp.async.wait_group %0;" :: "n"(N) : "memory")

__device__ __forceinline__ void sts_v2(uint32_t addr, float a, float b) {
    asm volatile("st.shared.v2.f32 [%0], {%1, %2};" :: "r"(addr), "f"(a), "f"(b));
}
__device__ __forceinline__ float4 lds_v4(uint32_t addr) {
    float4 v;
    asm volatile("ld.shared.v4.f32 {%0,%1,%2,%3}, [%4];"
                 : "=f"(v.x), "=f"(v.y), "=f"(v.z), "=f"(v.w) : "r"(addr));
    return v;
}

// ---------------------------------------------------------------------------
// kernel 1: fused prep — zero output+stats, feats->fp16, W transpose->fp16
// ---------------------------------------------------------------------------
__global__ void prep_kernel(float* __restrict__ out,
                            const float* __restrict__ feats,
                            const float* __restrict__ W) {
    const size_t stride = (size_t)gridDim.x * blockDim.x;
    const size_t base = (size_t)blockIdx.x * blockDim.x + threadIdx.x;

    float4 z = make_float4(0.f, 0.f, 0.f, 0.f);
    for (size_t i = base; i < (size_t)N_OUT * (C / 4); i += stride)
        ((float4*)out)[i] = z;

    for (size_t i = base; i < (size_t)N_IN * (C / 4); i += stride) {
        float4 v = ((const float4*)feats)[i];
        __half h[4];
        h[0] = __float2half_rn(v.x);
        h[1] = __float2half_rn(v.y);
        h[2] = __float2half_rn(v.z);
        h[3] = __float2half_rn(v.w);
        ((uint2*)g_fh)[i] = *(uint2*)h;
    }

    for (size_t i = base; i < (size_t)K3 * C * C; i += stride) {
        int c  = (int)(i & (C - 1));
        int nn = (int)((i >> 7) & (C - 1));
        int k  = (int)(i >> 14);
        g_wt[i] = __float2half_rn(W[(size_t)k * C * C + (size_t)c * C + nn]);
    }

    if (blockIdx.x == 0 && threadIdx.x < C) {
        g_sum[threadIdx.x]   = 0.f;
        g_sumsq[threadIdx.x] = 0.f;
    }
}

// ---------------------------------------------------------------------------
// kernel 2: persistent pipelined gather -> HMMA -> staged row-contig scatter
// grid: 294, block 256 (8 warps, 4x2 warp grid of 32x64 output tiles)
// ---------------------------------------------------------------------------
#define PAD_C   136
#define SM_MAPS 0                                 // 3 slots x 1024 B
#define SM_B    3072                              // 34816 B
#define SM_A0   (SM_B + C * PAD_C * 2)            // 37888
#define SM_A1   (SM_A0 + TILE_M * PAD_C * 2)      // 72704
#define SM_TOT  (SM_A1 + TILE_M * PAD_C * 2)      // 107520

__global__ void __launch_bounds__(NTHR, 2)
scatter_gemm(const int* __restrict__ in_maps,
             const int* __restrict__ out_maps,
             float*     __restrict__ out) {
    extern __shared__ char smem[];
    const uint32_t smb = smem_u32(smem);
    const int tid  = threadIdx.x;
    const int wid  = tid >> 5;
    const int lane = tid & 31;

    const int start = blockIdx.x * TPB;
    const int end   = min(start + TPB, TASKS);
    if (start >= end) return;

    // warp/lane constants
    const int wm = (wid & 3) * 32;
    const int wn = (wid >> 2) * 64;
    const uint32_t aOff = ((uint32_t)(wm + (lane & 15)) * PAD_C + ((lane >> 4) << 3)) * 2;
    const uint32_t bAddr = smb + SM_B
        + ((uint32_t)(wn + ((lane >> 4) << 3) + (lane & 7)) * PAD_C
           + (((lane >> 3) & 1) << 3)) * 2;

    // cp.async maps(j) into slot j%3 (zero-fill beyond MP tail)
    auto issue_maps = [&](int j) {
        if (tid < 64) {
            const int kq = j / NTILES, tq = j - kq * NTILES;
            const bool isOm = tid >= 32;
            const int c16 = tid & 31;
            const int* src = (isOm ? out_maps : in_maps)
                           + (size_t)kq * MP + (size_t)tq * TILE_M + c16 * 4;
            int nb = min(TILE_M, MP - tq * TILE_M) * 4 - c16 * 16;
            nb = nb < 0 ? 0 : (nb > 16 ? 16 : nb);
            cp16z(smb + SM_MAPS + (uint32_t)(j % 3) * 1024 + (isOm ? 512u : 0u)
                      + (uint32_t)c16 * 16, src, nb);
        }
    };
    // cp.async gather A(j) into buffer region abase using maps slot j%3
    auto issue_gather = [&](int j, uint32_t abase) {
        const int* imn = (const int*)(smem + SM_MAPS + (j % 3) * 1024);
#pragma unroll
        for (int it = 0; it < 2048 / NTHR; ++it) {
            int idx = it * NTHR + tid;
            int row = idx >> 4, c8 = idx & 15;
            cp16(abase + (uint32_t)(row * PAD_C + c8 * 8) * 2,
                 g_fh + (size_t)imn[row] * C + c8 * 8);
        }
    };

    // ---- prologue ----
    issue_maps(start);
    CP_COMMIT();
    CP_WAIT(0);
    __syncthreads();
    issue_gather(start, smb + SM_A0);
    if (start + 1 < end) issue_maps(start + 1);
    CP_COMMIT();

    int cur_k = -1;

    for (int i = start; i < end; ++i) {
        const int k = i / NTILES;
        const int t = i - k * NTILES;
        const int buf = i & 1;

        CP_WAIT(0);            // A(i) + maps(i+1) landed
        __syncthreads();       // cross-warp visibility; protects reused buffers

        if (k != cur_k) {      // <=2x per CTA
            const uint4* bg = (const uint4*)(g_wt + (size_t)k * C * C);
#pragma unroll
            for (int it = 0; it < 2048 / NTHR; ++it) {
                int idx = it * NTHR + tid;
                int row = idx >> 4, c8 = idx & 15;
                *(uint4*)(smem + SM_B + (row * PAD_C + c8 * 8) * 2) = bg[idx];
            }
            cur_k = k;
            __syncthreads();
        }

        // prefetch next tile: A(i+1) + maps(i+2)
        if (i + 1 < end) {
            issue_gather(i + 1, smb + (buf ? SM_A0 : SM_A1));
            if (i + 2 < end) issue_maps(i + 2);
            CP_COMMIT();
        }

        // ---- MMA mainloop on A[buf] ----
        const uint32_t aAddr = smb + (buf ? SM_A1 : SM_A0) + aOff;

        float acc[2][8][4];
#pragma unroll
        for (int mb = 0; mb < 2; ++mb)
#pragma unroll
            for (int nbt = 0; nbt < 8; ++nbt)
#pragma unroll
                for (int j = 0; j < 4; ++j) acc[mb][nbt][j] = 0.f;

#pragma unroll
        for (int ks = 0; ks < 8; ++ks) {
            const uint32_t kb = ks * 32;
            uint32_t a[2][4];
#pragma unroll
            for (int mb = 0; mb < 2; ++mb)
                ldsm_x4(a[mb][0], a[mb][1], a[mb][2], a[mb][3],
                        aAddr + mb * (16 * PAD_C * 2) + kb);
            uint32_t b[4][4];
#pragma unroll
            for (int g = 0; g < 4; ++g)
                ldsm_x4(b[g][0], b[g][1], b[g][2], b[g][3],
                        bAddr + g * (16 * PAD_C * 2) + kb);
#pragma unroll
            for (int mb = 0; mb < 2; ++mb)
#pragma unroll
                for (int g = 0; g < 4; ++g) {
                    mma16816(acc[mb][2 * g],     a[mb][0], a[mb][1], a[mb][2], a[mb][3],
                             b[g][0], b[g][1]);
                    mma16816(acc[mb][2 * g + 1], a[mb][0], a[mb][1], a[mb][2], a[mb][3],
                             b[g][2], b[g][3]);
                }
        }

        __syncthreads();       // A[buf] dead for ALL warps -> usable as staging

        // ---- epilogue: stage per-warp 16x64 fp32 halves, scatter row-contig ----
        const int* om = (const int*)(smem + SM_MAPS + (i % 3) * 1024) + 128;
        const int mvalid = min(TILE_M, MP - t * TILE_M);
        const uint32_t stage = smb + (buf ? SM_A1 : SM_A0) + (uint32_t)wid * 4096;

        const int rrA = lane >> 2;             // 0..7
        const int p   = lane & 3;
        const int jh  = p & 1;
        const int qr  = lane & 15;             // read: quad index
        const int rhf = lane >> 4;             // read: row half

#pragma unroll
        for (int mb = 0; mb < 2; ++mb) {
#pragma unroll
            for (int nbt = 0; nbt < 8; ++nbt) {
                const int qi = nbt * 2 + (p >> 1);
                const uint32_t sw = (uint32_t)((qi ^ rrA) & 15);   // rrA == rr&7 for both rows
                sts_v2(stage + (uint32_t)rrA * 256 + sw * 16 + (uint32_t)jh * 8,
                       acc[mb][nbt][0], acc[mb][nbt][1]);
                sts_v2(stage + (uint32_t)(rrA + 8) * 256 + sw * 16 + (uint32_t)jh * 8,
                       acc[mb][nbt][2], acc[mb][nbt][3]);
            }
            __syncwarp();
#pragma unroll
            for (int t8 = 0; t8 < 8; ++t8) {
                const int rr = t8 * 2 + rhf;
                float4 v = lds_v4(stage + (uint32_t)rr * 256
                                        + (uint32_t)((qr ^ (rr & 7)) & 15) * 16);
                const int grow = wm + mb * 16 + rr;
                if (grow < mvalid) {
                    float* dst = out + (size_t)om[grow] * C + wn + qr * 4;
                    red_v4(dst, v.x, v.y, v.z, v.w);
                }
            }
            __syncwarp();
        }
    }
}

// ---------------------------------------------------------------------------
// kernel 3: per-channel sum / sumsq
// ---------------------------------------------------------------------------
__global__ void stats_kernel(const float* __restrict__ out) {
    __shared__ float4 ssum[256];
    __shared__ float4 ssq[256];
    const int tid = threadIdx.x;
    const int c4  = tid & 31;
    const int g   = (blockIdx.x * 256 + tid) >> 5;
    const int ng  = (gridDim.x * 256) >> 5;

    float4 s = make_float4(0.f, 0.f, 0.f, 0.f);
    float4 q = make_float4(0.f, 0.f, 0.f, 0.f);
    const float4* o4 = (const float4*)out;
    for (int r = g; r < N_OUT; r += ng) {
        float4 v = o4[(size_t)r * 32 + c4];
        s.x += v.x; s.y += v.y; s.z += v.z; s.w += v.w;
        q.x += v.x * v.x; q.y += v.y * v.y; q.z += v.z * v.z; q.w += v.w * v.w;
    }
    ssum[tid] = s;
    ssq[tid]  = q;
    __syncthreads();
#pragma unroll
    for (int st = 128; st >= 32; st >>= 1) {
        if (tid < st) {
            ssum[tid].x += ssum[tid + st].x; ssum[tid].y += ssum[tid + st].y;
            ssum[tid].z += ssum[tid + st].z; ssum[tid].w += ssum[tid + st].w;
            ssq[tid].x  += ssq[tid + st].x;  ssq[tid].y  += ssq[tid + st].y;
            ssq[tid].z  += ssq[tid + st].z;  ssq[tid].w  += ssq[tid + st].w;
        }
        __syncthreads();
    }
    if (tid < 32) {
        atomicAdd(&g_sum[c4 * 4 + 0], ssum[tid].x);
        atomicAdd(&g_sum[c4 * 4 + 1], ssum[tid].y);
        atomicAdd(&g_sum[c4 * 4 + 2], ssum[tid].z);
        atomicAdd(&g_sum[c4 * 4 + 3], ssum[tid].w);
        atomicAdd(&g_sumsq[c4 * 4 + 0], ssq[tid].x);
        atomicAdd(&g_sumsq[c4 * 4 + 1], ssq[tid].y);
        atomicAdd(&g_sumsq[c4 * 4 + 2], ssq[tid].z);
        atomicAdd(&g_sumsq[c4 * 4 + 3], ssq[tid].w);
    }
}

// ---------------------------------------------------------------------------
// kernel 4: normalize (finalize folded in per-block)
// ---------------------------------------------------------------------------
__global__ void norm_kernel(float* __restrict__ out,
                            const float* __restrict__ gamma,
                            const float* __restrict__ beta) {
    __shared__ float sc[C], sh[C];
    if (threadIdx.x < C) {
        const int c = threadIdx.x;
        const float inv_n = 1.0f / (float)N_OUT;
        float mean = g_sum[c] * inv_n;
        float var  = g_sumsq[c] * inv_n - mean * mean;
        float s    = rsqrtf(var + EPS) * gamma[c];
        sc[c] = s;
        sh[c] = beta[c] - mean * s;
    }
    __syncthreads();

    const size_t n4 = (size_t)N_OUT * (C / 4);
    const size_t stride = (size_t)gridDim.x * blockDim.x;
    for (size_t i = (size_t)blockIdx.x * blockDim.x + threadIdx.x; i < n4; i += stride) {
        int c4 = (int)(i & 31);
        float4 v = ((float4*)out)[i];
        float4 s = *(float4*)(sc + c4 * 4);
        float4 h = *(float4*)(sh + c4 * 4);
        v.x = v.x * s.x + h.x;
        v.y = v.y * s.y + h.y;
        v.z = v.z * s.z + h.z;
        v.w = v.w * s.w + h.w;
        ((float4*)out)[i] = v;
    }
}

// ---------------------------------------------------------------------------
// launch
// ---------------------------------------------------------------------------
extern "C" void kernel_launch(void* const* d_in, const int* in_sizes, int n_in,
                              void* d_out, int out_size) {
    const float* feats    = (const float*)d_in[0];
    const float* W        = (const float*)d_in[1];
    const float* gamma    = (const float*)d_in[2];
    const float* beta     = (const float*)d_in[3];
    const int*   in_maps  = (const int*)d_in[4];
    const int*   out_maps = (const int*)d_in[5];
    float* out = (float*)d_out;

    cudaFuncSetAttribute(scatter_gemm,
                         cudaFuncAttributeMaxDynamicSharedMemorySize, SM_TOT);

    prep_kernel<<<1184, 256>>>(out, feats, W);
    scatter_gemm<<<GRID_MAIN, NTHR, SM_TOT>>>(in_maps, out_maps, out);
    stats_kernel<<<1184, 256>>>(out);
    norm_kernel<<<1184, 256>>>(out, gamma, beta);
}